// round 6
// baseline (speedup 1.0000x reference)
#include <cuda_runtime.h>

#define N_BATCH 4
#define C_TOTAL 2048
#define T_FR    8
#define HH      16
#define WW      16
#define R_ROIS  32
#define OUT_SZ  16
#define SCALE   (1.0f/16.0f)

#define C_PER    8
#define C_CHUNKS (C_TOTAL / C_PER)      // 256

#define PSTR     17                      // padded smem plane row stride
#define PLANE_SM (HH * PSTR)             // 272 floats per plane

#define OUT_ELEMS   (R_ROIS * C_TOTAL * OUT_SZ * OUT_SZ)   // 16777216
#define FEATP_ELEMS (N_BATCH * C_TOTAL * HH * WW)          // 2097152

// 3-tap (index, weight) table for one axis / output coordinate u.
// ratio=2: the two samples' floors differ by <=1, so the 4 bilinear taps fit
// in 3 consecutive cells {f0, f0+1, f0+2}; clamped duplicates just sum.
__device__ __forceinline__ void axis_taps3(float lo, float binsz, int u,
                                           int idx[3], float w[3]) {
    float g0  = ((float)(2 * u) + 0.5f) * 0.5f;
    float s0  = lo + g0 * binsz;
    float s1  = s0 + 0.5f * binsz;
    float vm0 = (s0 >= -1.0f && s0 <= 16.0f) ? 0.5f : 0.0f;
    float vm1 = (s1 >= -1.0f && s1 <= 16.0f) ? 0.5f : 0.0f;
    float x0  = fminf(fmaxf(s0, 0.0f), 15.0f);
    float x1  = fminf(fmaxf(s1, 0.0f), 15.0f);
    float f0  = floorf(x0);
    float f1  = floorf(x1);
    float l0  = x0 - f0;
    float l1  = x1 - f1;
    bool  same = (f1 == f0);
    w[0] = (1.0f - l0) * vm0 + (same ? (1.0f - l1) * vm1 : 0.0f);
    w[1] = l0 * vm0 + (same ? l1 * vm1 : (1.0f - l1) * vm1);
    w[2] = same ? 0.0f : l1 * vm1;
    int b  = (int)f0;
    idx[0] = b;
    idx[1] = min(b + 1, 15);
    idx[2] = min(b + 2, 15);
}

// ---------------------------------------------------------------------------
// Fused kernel: block = (8-channel chunk, batch nb).
// Phase 1: temporal mean of the chunk -> featp (gmem) + smem planes.
// Phase 2: for every roi in this batch, 3-tap separable RoIAlign:
//          y-pass from smem (conflict-free via pad 17), x-pass via shuffles.
// ---------------------------------------------------------------------------
__global__ __launch_bounds__(256) void fused_kernel(
        const float* __restrict__ feat,
        const float* __restrict__ rois,
        float* __restrict__ out,
        float* __restrict__ featp) {
    const int nb    = blockIdx.y;
    const int cbase = blockIdx.x * C_PER;
    const int tid   = threadIdx.x;

    __shared__ float planes[C_PER * PLANE_SM];   // 8.5 KB

    // ---------------- Phase 1: temporal mean ----------------
    {
        const int q   = tid & 63;      // float4 index within a plane
        const int c0  = tid >> 6;      // 0..3
        const int pix = q * 4;
        const int py  = pix >> 4;
        const int pxx = pix & 15;
        #pragma unroll
        for (int rep = 0; rep < 2; rep++) {
            const int c  = c0 + rep * 4;
            const long nc = (long)nb * C_TOTAL + cbase + c;
            const float4* src = (const float4*)feat + nc * (T_FR * 64) + q;
            float4 a = src[0];
            #pragma unroll
            for (int t = 1; t < T_FR; t++) {
                float4 v = src[t * 64];
                a.x += v.x; a.y += v.y; a.z += v.z; a.w += v.w;
            }
            a.x *= 0.125f; a.y *= 0.125f; a.z *= 0.125f; a.w *= 0.125f;
            ((float4*)featp)[nc * 64 + q] = a;
            float* sp = planes + c * PLANE_SM + py * PSTR + pxx;
            sp[0] = a.x; sp[1] = a.y; sp[2] = a.z; sp[3] = a.w;
        }
    }
    __syncthreads();

    // ---------------- Phase 2: RoIAlign over this batch's rois ----------------
    const int lx = tid & 15;     // output column j / y-pass column x
    const int ly = tid >> 4;     // output row i
    const int hi = tid & 16;     // half-warp selector

    for (int r = 0; r < R_ROIS; r++) {
        if ((int)rois[r * 5 + 0] != nb) continue;   // block-uniform branch

        const float bx1 = rois[r * 5 + 1] * SCALE - 0.5f;
        const float by1 = rois[r * 5 + 2] * SCALE - 0.5f;
        const float bx2 = rois[r * 5 + 3] * SCALE - 0.5f;
        const float by2 = rois[r * 5 + 4] * SCALE - 0.5f;
        const float bin_h = (by2 - by1) * (1.0f / OUT_SZ);
        const float bin_w = (bx2 - bx1) * (1.0f / OUT_SZ);

        int XI[3]; float WX[3];
        int YI[3]; float WY[3];
        axis_taps3(bx1, bin_w, lx, XI, WX);
        axis_taps3(by1, bin_h, ly, YI, WY);
        const int YR0 = YI[0] * PSTR + lx;
        const int YR1 = YI[1] * PSTR + lx;
        const int YR2 = YI[2] * PSTR + lx;
        const int S0  = hi | XI[0];
        const int S1  = hi | XI[1];
        const int S2  = hi | XI[2];

        float* opb = out + ((long)r * C_TOTAL + cbase) * (HH * WW) + tid;
        #pragma unroll
        for (int c = 0; c < C_PER; c++) {
            const float* pl = planes + c * PLANE_SM;
            float t;
            t =      WY[0] * pl[YR0];
            t = fmaf(WY[1], pl[YR1], t);
            t = fmaf(WY[2], pl[YR2], t);
            float v;
            v =      WX[0] * __shfl_sync(0xffffffffu, t, S0);
            v = fmaf(WX[1], __shfl_sync(0xffffffffu, t, S1), v);
            v = fmaf(WX[2], __shfl_sync(0xffffffffu, t, S2), v);
            opb[c * (HH * WW)] = v;
        }
    }
}

// ---------------------------------------------------------------------------
extern "C" void kernel_launch(void* const* d_in, const int* in_sizes, int n_in,
                              void* d_out, int out_size) {
    const float* feat = (const float*)d_in[0];
    const float* rois = (const float*)d_in[1];
    float* out   = (float*)d_out;
    float* featp = out + OUT_ELEMS;   // feat_p is the 2nd tuple element

    dim3 grid(C_CHUNKS, N_BATCH);     // 256 x 4 = 1024 blocks
    fused_kernel<<<grid, 256>>>(feat, rois, out, featp);
}

// round 7
// speedup vs baseline: 1.0073x; 1.0073x over previous
#include <cuda_runtime.h>

#define N_BATCH 4
#define C_TOTAL 2048
#define T_FR    8
#define HH      16
#define WW      16
#define R_ROIS  32
#define OUT_SZ  16
#define SCALE   (1.0f/16.0f)

#define C_PER    4
#define C_CHUNKS (C_TOTAL / C_PER)      // 512

#define PSTR     17                      // padded smem plane row stride
#define PLANE_SM (HH * PSTR)             // 272 floats per plane

#define OUT_ELEMS   (R_ROIS * C_TOTAL * OUT_SZ * OUT_SZ)   // 16777216
#define FEATP_ELEMS (N_BATCH * C_TOTAL * HH * WW)          // 2097152

// Per-(roi, coord, axis) tap record: 3 merged weights + base cell index.
struct TapRec { float w0, w1, w2; int b; };
__device__ TapRec g_xtap[R_ROIS * 16];
__device__ TapRec g_ytap[R_ROIS * 16];
__device__ int    g_nb[R_ROIS];

// 3-tap (index, weight) table for one axis / output coordinate u.
// ratio=2: the two samples' floors differ by <=1, so the 4 bilinear taps fit
// in 3 consecutive cells {b, b+1, b+2}; clamped duplicates just sum weights.
__device__ __forceinline__ void axis_taps3(float lo, float binsz, int u,
                                           int* bout, float w[3]) {
    float g0  = ((float)(2 * u) + 0.5f) * 0.5f;
    float s0  = lo + g0 * binsz;
    float s1  = s0 + 0.5f * binsz;
    float vm0 = (s0 >= -1.0f && s0 <= 16.0f) ? 0.5f : 0.0f;
    float vm1 = (s1 >= -1.0f && s1 <= 16.0f) ? 0.5f : 0.0f;
    float x0  = fminf(fmaxf(s0, 0.0f), 15.0f);
    float x1  = fminf(fmaxf(s1, 0.0f), 15.0f);
    float f0  = floorf(x0);
    float f1  = floorf(x1);
    float l0  = x0 - f0;
    float l1  = x1 - f1;
    bool  same = (f1 == f0);
    w[0] = (1.0f - l0) * vm0 + (same ? (1.0f - l1) * vm1 : 0.0f);
    w[1] = l0 * vm0 + (same ? l1 * vm1 : (1.0f - l1) * vm1);
    w[2] = same ? 0.0f : l1 * vm1;
    *bout = (int)f0;
}

// ---------------------------------------------------------------------------
// Kernel 0: precompute tap tables (one tiny block).
// ---------------------------------------------------------------------------
__global__ void taps_kernel(const float* __restrict__ rois) {
    int t = threadIdx.x;
    if (t >= R_ROIS * 16) return;
    int r = t >> 4, u = t & 15;
    float bx1 = rois[r * 5 + 1] * SCALE - 0.5f;
    float by1 = rois[r * 5 + 2] * SCALE - 0.5f;
    float bx2 = rois[r * 5 + 3] * SCALE - 0.5f;
    float by2 = rois[r * 5 + 4] * SCALE - 0.5f;
    float bin_w = (bx2 - bx1) * (1.0f / OUT_SZ);
    float bin_h = (by2 - by1) * (1.0f / OUT_SZ);
    int b; float w[3];
    axis_taps3(bx1, bin_w, u, &b, w);
    g_xtap[t] = TapRec{w[0], w[1], w[2], b};
    axis_taps3(by1, bin_h, u, &b, w);
    g_ytap[t] = TapRec{w[0], w[1], w[2], b};
    if (u == 0) g_nb[r] = (int)rois[r * 5 + 0];
}

// ---------------------------------------------------------------------------
// Kernel 1 (fused): block = (4-channel chunk, batch nb), 256 threads.
// Phase 1: temporal mean of the chunk -> featp (gmem) + smem planes (pad 17).
// Phase 2: for each roi of this batch: load tap records (2x LDG.128),
//          3-tap y-pass from smem, 3-shuffle x-pass, coalesced store.
// ---------------------------------------------------------------------------
__global__ __launch_bounds__(256) void fused_kernel(
        const float* __restrict__ feat,
        float* __restrict__ out,
        float* __restrict__ featp) {
    const int nb    = blockIdx.y;
    const int cbase = blockIdx.x * C_PER;
    const int tid   = threadIdx.x;

    __shared__ float planes[C_PER * PLANE_SM];   // 4.25 KB

    // ---------------- Phase 1: temporal mean ----------------
    {
        const int c   = tid >> 6;          // 0..3
        const int q   = tid & 63;          // float4 index within plane
        const int py  = q >> 2;
        const int pxx = (q & 3) * 4;
        const long nc = (long)nb * C_TOTAL + cbase + c;
        const float4* src = (const float4*)feat + nc * (T_FR * 64) + q;
        float4 a = src[0];
        #pragma unroll
        for (int t = 1; t < T_FR; t++) {
            float4 v = src[t * 64];
            a.x += v.x; a.y += v.y; a.z += v.z; a.w += v.w;
        }
        a.x *= 0.125f; a.y *= 0.125f; a.z *= 0.125f; a.w *= 0.125f;
        ((float4*)featp)[nc * 64 + q] = a;
        float* sp = planes + c * PLANE_SM + py * PSTR + pxx;
        sp[0] = a.x; sp[1] = a.y; sp[2] = a.z; sp[3] = a.w;
    }
    __syncthreads();

    // ---------------- Phase 2: RoIAlign ----------------
    const int lx = tid & 15;
    const int ly = tid >> 4;
    const int hi = tid & 16;
    const float4* xt = reinterpret_cast<const float4*>(g_xtap);
    const float4* yt = reinterpret_cast<const float4*>(g_ytap);

    for (int r = 0; r < R_ROIS; r++) {
        if (g_nb[r] != nb) continue;       // block-uniform branch

        float4 vx = __ldg(xt + r * 16 + lx);   // {wx0,wx1,wx2, xbase}
        float4 vy = __ldg(yt + r * 16 + ly);   // {wy0,wy1,wy2, ybase}
        const int yb  = __float_as_int(vy.w);
        const int YR0 = yb * PSTR + lx;
        const int YR1 = min(yb + 1, 15) * PSTR + lx;
        const int YR2 = min(yb + 2, 15) * PSTR + lx;
        const int xb  = __float_as_int(vx.w);
        const int S0  = hi | xb;
        const int S1  = hi | min(xb + 1, 15);
        const int S2  = hi | min(xb + 2, 15);

        float* opb = out + ((long)r * C_TOTAL + cbase) * (HH * WW) + tid;
        #pragma unroll
        for (int c = 0; c < C_PER; c++) {
            const float* pl = planes + c * PLANE_SM;
            float t;
            t =      vy.x * pl[YR0];
            t = fmaf(vy.y,  pl[YR1], t);
            t = fmaf(vy.z,  pl[YR2], t);
            float v;
            v =      vx.x * __shfl_sync(0xffffffffu, t, S0);
            v = fmaf(vx.y,  __shfl_sync(0xffffffffu, t, S1), v);
            v = fmaf(vx.z,  __shfl_sync(0xffffffffu, t, S2), v);
            opb[c * (HH * WW)] = v;
        }
    }
}

// ---------------------------------------------------------------------------
extern "C" void kernel_launch(void* const* d_in, const int* in_sizes, int n_in,
                              void* d_out, int out_size) {
    const float* feat = (const float*)d_in[0];
    const float* rois = (const float*)d_in[1];
    float* out   = (float*)d_out;
    float* featp = out + OUT_ELEMS;   // feat_p is the 2nd tuple element

    taps_kernel<<<1, R_ROIS * 16>>>(rois);
    dim3 grid(C_CHUNKS, N_BATCH);     // 512 x 4 = 2048 blocks
    fused_kernel<<<grid, 256>>>(feat, out, featp);
}

// round 8
// speedup vs baseline: 1.0544x; 1.0468x over previous
#include <cuda_runtime.h>

#define N_BATCH 4
#define C_TOTAL 2048
#define T_FR    8
#define HH      16
#define WW      16
#define R_ROIS  32
#define OUT_SZ  16
#define SCALE   (1.0f/16.0f)

#define C_PER    4
#define C_CHUNKS (C_TOTAL / C_PER)      // 512

#define PSTR     17                      // padded smem plane row stride
#define PLANE_SM (HH * PSTR)             // 272 floats per plane

#define OUT_ELEMS   (R_ROIS * C_TOTAL * OUT_SZ * OUT_SZ)   // 16777216
#define FEATP_ELEMS (N_BATCH * C_TOTAL * HH * WW)          // 2097152

// 3-tap merged weights for one axis / output coordinate u.
// ratio=2: the two samples' floors differ by <=1 -> 4 bilinear taps fit in
// 3 consecutive cells {b, b+1, b+2}; clamped duplicates just sum weights.
__device__ __forceinline__ float4 axis_taps3(float lo, float binsz, int u) {
    float g0  = ((float)(2 * u) + 0.5f) * 0.5f;
    float s0  = lo + g0 * binsz;
    float s1  = s0 + 0.5f * binsz;
    float vm0 = (s0 >= -1.0f && s0 <= 16.0f) ? 0.5f : 0.0f;
    float vm1 = (s1 >= -1.0f && s1 <= 16.0f) ? 0.5f : 0.0f;
    float x0  = fminf(fmaxf(s0, 0.0f), 15.0f);
    float x1  = fminf(fmaxf(s1, 0.0f), 15.0f);
    float f0  = floorf(x0);
    float f1  = floorf(x1);
    float l0  = x0 - f0;
    float l1  = x1 - f1;
    bool  same = (f1 == f0);
    float4 rec;
    rec.x = (1.0f - l0) * vm0 + (same ? (1.0f - l1) * vm1 : 0.0f);
    rec.y = l0 * vm0 + (same ? l1 * vm1 : (1.0f - l1) * vm1);
    rec.z = same ? 0.0f : l1 * vm1;
    rec.w = __int_as_float((int)f0);
    return rec;
}

// ---------------------------------------------------------------------------
// Single fused kernel. Block = (4-channel chunk, batch nb), 256 threads.
// Phase 0: cooperatively build the full tap table (32 rois x 16 coords x 2
//          axes) in shared memory (~2 records/axis per thread, once/block).
// Phase 1: temporal mean of the chunk -> featp (gmem) + smem planes (pad 17).
// (one __syncthreads)
// Phase 2: for each roi of this batch: 2x LDS.128 tap records,
//          3-tap y-pass from smem planes, 3-shuffle x-pass, coalesced store.
// ---------------------------------------------------------------------------
__global__ __launch_bounds__(256) void fused_kernel(
        const float* __restrict__ feat,
        const float* __restrict__ rois,
        float* __restrict__ out,
        float* __restrict__ featp) {
    const int nb    = blockIdx.y;
    const int cbase = blockIdx.x * C_PER;
    const int tid   = threadIdx.x;

    __shared__ float4 s_xtap[R_ROIS * 16];          // 8 KB
    __shared__ float4 s_ytap[R_ROIS * 16];          // 8 KB
    __shared__ float  planes[C_PER * PLANE_SM];     // 4.25 KB
    __shared__ int    s_nb[R_ROIS];

    // ---------------- Phase 0: tap table ----------------
    #pragma unroll
    for (int k = tid; k < R_ROIS * 16; k += 256) {  // 2 iterations
        const int r = k >> 4, u = k & 15;
        const float bx1 = rois[r * 5 + 1] * SCALE - 0.5f;
        const float by1 = rois[r * 5 + 2] * SCALE - 0.5f;
        const float bx2 = rois[r * 5 + 3] * SCALE - 0.5f;
        const float by2 = rois[r * 5 + 4] * SCALE - 0.5f;
        s_xtap[k] = axis_taps3(bx1, (bx2 - bx1) * (1.0f / OUT_SZ), u);
        s_ytap[k] = axis_taps3(by1, (by2 - by1) * (1.0f / OUT_SZ), u);
        if (u == 0) s_nb[r] = (int)rois[r * 5 + 0];
    }

    // ---------------- Phase 1: temporal mean ----------------
    {
        const int c   = tid >> 6;          // 0..3
        const int q   = tid & 63;          // float4 index within plane
        const int py  = q >> 2;
        const int pxx = (q & 3) * 4;
        const long nc = (long)nb * C_TOTAL + cbase + c;
        const float4* src = (const float4*)feat + nc * (T_FR * 64) + q;
        float4 a = src[0];
        #pragma unroll
        for (int t = 1; t < T_FR; t++) {
            float4 v = src[t * 64];
            a.x += v.x; a.y += v.y; a.z += v.z; a.w += v.w;
        }
        a.x *= 0.125f; a.y *= 0.125f; a.z *= 0.125f; a.w *= 0.125f;
        ((float4*)featp)[nc * 64 + q] = a;
        float* sp = planes + c * PLANE_SM + py * PSTR + pxx;
        sp[0] = a.x; sp[1] = a.y; sp[2] = a.z; sp[3] = a.w;
    }
    __syncthreads();

    // ---------------- Phase 2: RoIAlign ----------------
    const int lx = tid & 15;
    const int ly = tid >> 4;
    const int hi = tid & 16;

    for (int r = 0; r < R_ROIS; r++) {
        if (s_nb[r] != nb) continue;       // block-uniform branch

        const float4 vx = s_xtap[r * 16 + lx];   // {wx0,wx1,wx2, xbase}
        const float4 vy = s_ytap[r * 16 + ly];   // {wy0,wy1,wy2, ybase}
        const int yb  = __float_as_int(vy.w);
        const int YR0 = yb * PSTR + lx;
        const int YR1 = min(yb + 1, 15) * PSTR + lx;
        const int YR2 = min(yb + 2, 15) * PSTR + lx;
        const int xb  = __float_as_int(vx.w);
        const int S0  = hi | xb;
        const int S1  = hi | min(xb + 1, 15);
        const int S2  = hi | min(xb + 2, 15);

        float* opb = out + ((long)r * C_TOTAL + cbase) * (HH * WW) + tid;
        #pragma unroll
        for (int c = 0; c < C_PER; c++) {
            const float* pl = planes + c * PLANE_SM;
            float t;
            t =      vy.x * pl[YR0];
            t = fmaf(vy.y,  pl[YR1], t);
            t = fmaf(vy.z,  pl[YR2], t);
            float v;
            v =      vx.x * __shfl_sync(0xffffffffu, t, S0);
            v = fmaf(vx.y,  __shfl_sync(0xffffffffu, t, S1), v);
            v = fmaf(vx.z,  __shfl_sync(0xffffffffu, t, S2), v);
            opb[c * (HH * WW)] = v;
        }
    }
}

// ---------------------------------------------------------------------------
extern "C" void kernel_launch(void* const* d_in, const int* in_sizes, int n_in,
                              void* d_out, int out_size) {
    const float* feat = (const float*)d_in[0];
    const float* rois = (const float*)d_in[1];
    float* out   = (float*)d_out;
    float* featp = out + OUT_ELEMS;   // feat_p is the 2nd tuple element

    dim3 grid(C_CHUNKS, N_BATCH);     // 512 x 4 = 2048 blocks
    fused_kernel<<<grid, 256>>>(feat, rois, out, featp);
}

// round 9
// speedup vs baseline: 1.1366x; 1.0779x over previous
#include <cuda_runtime.h>

#define N_BATCH 4
#define C_TOTAL 2048
#define T_FR    8
#define HH      16
#define WW      16
#define R_ROIS  32
#define OUT_SZ  16
#define SCALE   (1.0f/16.0f)

#define C_PER    8
#define C_CHUNKS (C_TOTAL / C_PER)      // 256

#define PSTR     17                      // padded smem plane row stride
#define PLANE_SM (HH * PSTR)             // 272 floats per plane

#define OUT_ELEMS   (R_ROIS * C_TOTAL * OUT_SZ * OUT_SZ)   // 16777216
#define FEATP_ELEMS (N_BATCH * C_TOTAL * HH * WW)          // 2097152

// 3-tap merged weights for one axis / output coordinate u, with the three
// clamped cell offsets pre-packed into an int (8 bits each) in .w.
// ratio=2: two samples' floors differ by <=1 -> 4 bilinear taps fit in 3
// consecutive cells {b, b+1, b+2}; clamped duplicates just sum weights.
__device__ __forceinline__ float4 axis_taps3(float lo, float binsz, int u,
                                             int mulstep) {
    float g0  = ((float)(2 * u) + 0.5f) * 0.5f;
    float s0  = lo + g0 * binsz;
    float s1  = s0 + 0.5f * binsz;
    float vm0 = (s0 >= -1.0f && s0 <= 16.0f) ? 0.5f : 0.0f;
    float vm1 = (s1 >= -1.0f && s1 <= 16.0f) ? 0.5f : 0.0f;
    float x0  = fminf(fmaxf(s0, 0.0f), 15.0f);
    float x1  = fminf(fmaxf(s1, 0.0f), 15.0f);
    float f0  = floorf(x0);
    float f1  = floorf(x1);
    float l0  = x0 - f0;
    float l1  = x1 - f1;
    bool  same = (f1 == f0);
    float4 rec;
    rec.x = (1.0f - l0) * vm0 + (same ? (1.0f - l1) * vm1 : 0.0f);
    rec.y = l0 * vm0 + (same ? l1 * vm1 : (1.0f - l1) * vm1);
    rec.z = same ? 0.0f : l1 * vm1;
    int b  = (int)f0;
    int o0 = b * mulstep;
    int o1 = min(b + 1, 15) * mulstep;
    int o2 = min(b + 2, 15) * mulstep;
    rec.w = __int_as_float(o0 | (o1 << 8) | (o2 << 16));
    return rec;
}

// ---------------------------------------------------------------------------
// Single fused kernel. Block = (8-channel chunk, batch nb), 256 threads.
// Phase 0: build tap table (32 rois x 16 coords x 2 axes, offsets packed) in
//          smem + warp-ballot compacted list of this batch's rois.
// Phase 1: temporal mean of the chunk -> featp (gmem, streaming) + smem
//          planes (pad 17).   (one __syncthreads)
// Phase 2: per matched roi: 2x LDS.128 tap records, 3-tap y-pass from smem,
//          3-shuffle x-pass, coalesced streaming store.
// ---------------------------------------------------------------------------
__global__ __launch_bounds__(256) void fused_kernel(
        const float* __restrict__ feat,
        const float* __restrict__ rois,
        float* __restrict__ out,
        float* __restrict__ featp) {
    const int nb    = blockIdx.y;
    const int cbase = blockIdx.x * C_PER;
    const int tid   = threadIdx.x;

    __shared__ float4 s_xtap[R_ROIS * 16];          // 8 KB
    __shared__ float4 s_ytap[R_ROIS * 16];          // 8 KB
    __shared__ float  planes[C_PER * PLANE_SM];     // 8.5 KB
    __shared__ int    s_list[R_ROIS];
    __shared__ int    s_cnt;

    // ---------------- Phase 0: tap table + roi list ----------------
    #pragma unroll
    for (int k = tid; k < R_ROIS * 16; k += 256) {  // 2 iterations
        const int r = k >> 4, u = k & 15;
        const float bx1 = rois[r * 5 + 1] * SCALE - 0.5f;
        const float by1 = rois[r * 5 + 2] * SCALE - 0.5f;
        const float bx2 = rois[r * 5 + 3] * SCALE - 0.5f;
        const float by2 = rois[r * 5 + 4] * SCALE - 0.5f;
        s_xtap[k] = axis_taps3(bx1, (bx2 - bx1) * (1.0f / OUT_SZ), u, 1);
        s_ytap[k] = axis_taps3(by1, (by2 - by1) * (1.0f / OUT_SZ), u, PSTR);
    }
    if (tid < 32) {
        int match = ((int)rois[tid * 5 + 0] == nb);
        unsigned m = __ballot_sync(0xffffffffu, match);
        if (match) {
            int pos = __popc(m & ((1u << tid) - 1u));
            s_list[pos] = tid;
        }
        if (tid == 0) s_cnt = __popc(m);
    }

    // ---------------- Phase 1: temporal mean ----------------
    {
        const int c0  = tid >> 6;          // 0..3
        const int q   = tid & 63;          // float4 index within plane
        const int py  = q >> 2;
        const int pxx = (q & 3) * 4;
        #pragma unroll
        for (int rep = 0; rep < 2; rep++) {
            const int c  = c0 + rep * 4;
            const long nc = (long)nb * C_TOTAL + cbase + c;
            const float4* src = (const float4*)feat + nc * (T_FR * 64) + q;
            float4 a = src[0];
            #pragma unroll
            for (int t = 1; t < T_FR; t++) {
                float4 v = src[t * 64];
                a.x += v.x; a.y += v.y; a.z += v.z; a.w += v.w;
            }
            a.x *= 0.125f; a.y *= 0.125f; a.z *= 0.125f; a.w *= 0.125f;
            __stcs((float4*)featp + nc * 64 + q, a);
            float* sp = planes + c * PLANE_SM + py * PSTR + pxx;
            sp[0] = a.x; sp[1] = a.y; sp[2] = a.z; sp[3] = a.w;
        }
    }
    __syncthreads();

    // ---------------- Phase 2: RoIAlign over matched rois ----------------
    const int lx = tid & 15;
    const int ly = tid >> 4;
    const int hi = tid & 16;
    const int nr = s_cnt;

    for (int i = 0; i < nr; i++) {
        const int r = s_list[i];
        const float4 vx = s_xtap[r * 16 + lx];   // {wx0,wx1,wx2, packed lanes}
        const float4 vy = s_ytap[r * 16 + ly];   // {wy0,wy1,wy2, packed offs}
        const int py_ = __float_as_int(vy.w);
        const int YR0 = (py_        & 255) + lx;
        const int YR1 = ((py_ >> 8) & 255) + lx;
        const int YR2 = ((py_ >> 16)& 255) + lx;
        const int px_ = __float_as_int(vx.w);
        const int S0  = hi | (px_        & 255);
        const int S1  = hi | ((px_ >> 8) & 255);
        const int S2  = hi | ((px_ >> 16)& 255);

        float* opb = out + ((long)r * C_TOTAL + cbase) * (HH * WW) + tid;
        #pragma unroll
        for (int c = 0; c < C_PER; c++) {
            const float* pl = planes + c * PLANE_SM;
            float t;
            t =      vy.x * pl[YR0];
            t = fmaf(vy.y,  pl[YR1], t);
            t = fmaf(vy.z,  pl[YR2], t);
            float v;
            v =      vx.x * __shfl_sync(0xffffffffu, t, S0);
            v = fmaf(vx.y,  __shfl_sync(0xffffffffu, t, S1), v);
            v = fmaf(vx.z,  __shfl_sync(0xffffffffu, t, S2), v);
            __stcs(opb + c * (HH * WW), v);
        }
    }
}

// ---------------------------------------------------------------------------
extern "C" void kernel_launch(void* const* d_in, const int* in_sizes, int n_in,
                              void* d_out, int out_size) {
    const float* feat = (const float*)d_in[0];
    const float* rois = (const float*)d_in[1];
    float* out   = (float*)d_out;
    float* featp = out + OUT_ELEMS;   // feat_p is the 2nd tuple element

    dim3 grid(C_CHUNKS, N_BATCH);     // 256 x 4 = 1024 blocks
    fused_kernel<<<grid, 256>>>(feat, rois, out, featp);
}

// round 10
// speedup vs baseline: 1.1923x; 1.0490x over previous
#include <cuda_runtime.h>

#define N_BATCH 4
#define C_TOTAL 2048
#define T_FR    8
#define HH      16
#define WW      16
#define R_ROIS  32
#define OUT_SZ  16
#define SCALE   (1.0f/16.0f)

#define C_PER    8
#define HALF     4
#define C_CHUNKS (C_TOTAL / C_PER)      // 256

#define PSTR     17                      // padded smem plane row stride
#define PLANE_SM (HH * PSTR)             // 272 floats per plane

#define OUT_ELEMS   (R_ROIS * C_TOTAL * OUT_SZ * OUT_SZ)   // 16777216
#define FEATP_ELEMS (N_BATCH * C_TOTAL * HH * WW)          // 2097152

// 3-tap merged weights for one axis / output coordinate u; the three clamped
// cell offsets (scaled by mulstep) are packed 8-bit each into .w.
// ratio=2: two samples' floors differ by <=1 -> 4 bilinear taps fit in 3
// consecutive cells {b, b+1, b+2}; clamped duplicates just sum weights.
__device__ __forceinline__ float4 axis_taps3(float lo, float binsz, int u,
                                             int mulstep) {
    float g0  = ((float)(2 * u) + 0.5f) * 0.5f;
    float s0  = lo + g0 * binsz;
    float s1  = s0 + 0.5f * binsz;
    float vm0 = (s0 >= -1.0f && s0 <= 16.0f) ? 0.5f : 0.0f;
    float vm1 = (s1 >= -1.0f && s1 <= 16.0f) ? 0.5f : 0.0f;
    float x0  = fminf(fmaxf(s0, 0.0f), 15.0f);
    float x1  = fminf(fmaxf(s1, 0.0f), 15.0f);
    float f0  = floorf(x0);
    float f1  = floorf(x1);
    float l0  = x0 - f0;
    float l1  = x1 - f1;
    bool  same = (f1 == f0);
    float4 rec;
    rec.x = (1.0f - l0) * vm0 + (same ? (1.0f - l1) * vm1 : 0.0f);
    rec.y = l0 * vm0 + (same ? l1 * vm1 : (1.0f - l1) * vm1);
    rec.z = same ? 0.0f : l1 * vm1;
    int b  = (int)f0;
    int o0 = b * mulstep;
    int o1 = min(b + 1, 15) * mulstep;
    int o2 = min(b + 2, 15) * mulstep;
    rec.w = __int_as_float(o0 | (o1 << 8) | (o2 << 16));
    return rec;
}

// ---------------------------------------------------------------------------
// Single fused, software-pipelined kernel.
// Block = (8-channel chunk, batch nb), 256 threads; chunk split in 2 halves.
//   LDG(h0) -> taps+ballot -> reduce h0 -> LDG(h1) -> STS h0 -> sync
//   -> roi(h0) [h1 in flight] -> reduce h1 -> STS h1 -> sync -> roi(h1)
// ---------------------------------------------------------------------------
__global__ __launch_bounds__(256) void fused_kernel(
        const float* __restrict__ feat,
        const float* __restrict__ rois,
        float* __restrict__ out,
        float* __restrict__ featp) {
    const int nb    = blockIdx.y;
    const int cbase = blockIdx.x * C_PER;
    const int tid   = threadIdx.x;

    __shared__ float4 s_xtap[R_ROIS * 16];              // 8 KB
    __shared__ float4 s_ytap[R_ROIS * 16];              // 8 KB
    __shared__ float  planes[2][HALF * PLANE_SM];       // 8.7 KB
    __shared__ int    s_list[R_ROIS];
    __shared__ int    s_cnt;

    // load mapping: one channel (of 4 per half) x one float4 pixel group
    const int c    = tid >> 6;          // 0..3
    const int q    = tid & 63;
    const int ppy  = q >> 2;
    const int ppx  = (q & 3) * 4;
    const long nc0 = (long)nb * C_TOTAL + cbase + c;
    const float4* f4   = (const float4*)feat;
    const float4* src0 = f4 + nc0 * (T_FR * 64) + q;
    float*  sp0 = &planes[0][c * PLANE_SM + ppy * PSTR + ppx];
    float*  sp1 = &planes[1][c * PLANE_SM + ppy * PSTR + ppx];

    // ---- issue half-0 loads ----
    float4 L[T_FR];
    #pragma unroll
    for (int t = 0; t < T_FR; t++) L[t] = __ldg(src0 + t * 64);

    // ---- tap table + roi list (overlaps h0 load latency) ----
    #pragma unroll
    for (int k = tid; k < R_ROIS * 16; k += 256) {
        const int r = k >> 4, u = k & 15;
        const float bx1 = rois[r * 5 + 1] * SCALE - 0.5f;
        const float by1 = rois[r * 5 + 2] * SCALE - 0.5f;
        const float bx2 = rois[r * 5 + 3] * SCALE - 0.5f;
        const float by2 = rois[r * 5 + 4] * SCALE - 0.5f;
        s_xtap[k] = axis_taps3(bx1, (bx2 - bx1) * (1.0f / OUT_SZ), u, 1);
        s_ytap[k] = axis_taps3(by1, (by2 - by1) * (1.0f / OUT_SZ), u, PSTR);
    }
    if (tid < 32) {
        int match = ((int)rois[tid * 5 + 0] == nb);
        unsigned m = __ballot_sync(0xffffffffu, match);
        if (match) s_list[__popc(m & ((1u << tid) - 1u))] = tid;
        if (tid == 0) s_cnt = __popc(m);
    }

    // ---- reduce half 0, write featp, start half-1 loads, stage smem ----
    float4 a = L[0];
    #pragma unroll
    for (int t = 1; t < T_FR; t++) {
        a.x += L[t].x; a.y += L[t].y; a.z += L[t].z; a.w += L[t].w;
    }
    a.x *= 0.125f; a.y *= 0.125f; a.z *= 0.125f; a.w *= 0.125f;
    __stcs((float4*)featp + nc0 * 64 + q, a);

    const float4* src1 = src0 + (long)HALF * (T_FR * 64);
    #pragma unroll
    for (int t = 0; t < T_FR; t++) L[t] = __ldg(src1 + t * 64);

    sp0[0] = a.x; sp0[1] = a.y; sp0[2] = a.z; sp0[3] = a.w;
    __syncthreads();

    // ---- roi compute, half 0 (h1 loads in flight) ----
    const int lx = tid & 15;
    const int ly = tid >> 4;
    const int hi = tid & 16;
    const int nr = s_cnt;

    for (int i = 0; i < nr; i++) {
        const int r = s_list[i];
        const float4 vx = s_xtap[r * 16 + lx];
        const float4 vy = s_ytap[r * 16 + ly];
        const int pk = __float_as_int(vy.w);
        const int YR0 = (pk & 255) + lx;
        const int YR1 = ((pk >> 8) & 255) + lx;
        const int YR2 = ((pk >> 16) & 255) + lx;
        const int xk = __float_as_int(vx.w);
        const int S0 = hi | (xk & 255);
        const int S1 = hi | ((xk >> 8) & 255);
        const int S2 = hi | ((xk >> 16) & 255);
        float* opb = out + ((long)r * C_TOTAL + cbase) * (HH * WW) + tid;
        #pragma unroll
        for (int cc = 0; cc < HALF; cc++) {
            const float* pl = &planes[0][cc * PLANE_SM];
            float t;
            t =      vy.x * pl[YR0];
            t = fmaf(vy.y,  pl[YR1], t);
            t = fmaf(vy.z,  pl[YR2], t);
            float v;
            v =      vx.x * __shfl_sync(0xffffffffu, t, S0);
            v = fmaf(vx.y,  __shfl_sync(0xffffffffu, t, S1), v);
            v = fmaf(vx.z,  __shfl_sync(0xffffffffu, t, S2), v);
            __stcs(opb + cc * (HH * WW), v);
        }
    }

    // ---- reduce half 1, stage smem ----
    float4 b = L[0];
    #pragma unroll
    for (int t = 1; t < T_FR; t++) {
        b.x += L[t].x; b.y += L[t].y; b.z += L[t].z; b.w += L[t].w;
    }
    b.x *= 0.125f; b.y *= 0.125f; b.z *= 0.125f; b.w *= 0.125f;
    __stcs((float4*)featp + (nc0 + HALF) * 64 + q, b);
    sp1[0] = b.x; sp1[1] = b.y; sp1[2] = b.z; sp1[3] = b.w;
    __syncthreads();

    // ---- roi compute, half 1 ----
    for (int i = 0; i < nr; i++) {
        const int r = s_list[i];
        const float4 vx = s_xtap[r * 16 + lx];
        const float4 vy = s_ytap[r * 16 + ly];
        const int pk = __float_as_int(vy.w);
        const int YR0 = (pk & 255) + lx;
        const int YR1 = ((pk >> 8) & 255) + lx;
        const int YR2 = ((pk >> 16) & 255) + lx;
        const int xk = __float_as_int(vx.w);
        const int S0 = hi | (xk & 255);
        const int S1 = hi | ((xk >> 8) & 255);
        const int S2 = hi | ((xk >> 16) & 255);
        float* opb = out + ((long)r * C_TOTAL + cbase + HALF) * (HH * WW) + tid;
        #pragma unroll
        for (int cc = 0; cc < HALF; cc++) {
            const float* pl = &planes[1][cc * PLANE_SM];
            float t;
            t =      vy.x * pl[YR0];
            t = fmaf(vy.y,  pl[YR1], t);
            t = fmaf(vy.z,  pl[YR2], t);
            float v;
            v =      vx.x * __shfl_sync(0xffffffffu, t, S0);
            v = fmaf(vx.y,  __shfl_sync(0xffffffffu, t, S1), v);
            v = fmaf(vx.z,  __shfl_sync(0xffffffffu, t, S2), v);
            __stcs(opb + cc * (HH * WW), v);
        }
    }
}

// ---------------------------------------------------------------------------
extern "C" void kernel_launch(void* const* d_in, const int* in_sizes, int n_in,
                              void* d_out, int out_size) {
    const float* feat = (const float*)d_in[0];
    const float* rois = (const float*)d_in[1];
    float* out   = (float*)d_out;
    float* featp = out + OUT_ELEMS;   // feat_p is the 2nd tuple element

    dim3 grid(C_CHUNKS, N_BATCH);     // 256 x 4 = 1024 blocks
    fused_kernel<<<grid, 256>>>(feat, rois, out, featp);
}

// round 11
// speedup vs baseline: 1.2705x; 1.0656x over previous
#include <cuda_runtime.h>

#define N_BATCH 4
#define C_TOTAL 2048
#define T_FR    8
#define HH      16
#define WW      16
#define R_ROIS  32
#define OUT_SZ  16
#define SCALE   (1.0f/16.0f)

#define C_PER    8
#define HALF     4
#define NPAIR    (HALF / 2)              // 2 float2 plane-pairs per half
#define C_CHUNKS (C_TOTAL / C_PER)       // 256

#define PSTR     17                       // padded plane row stride (float2!)
#define PLANE_SM (HH * PSTR)              // 272 float2 per pair-plane

#define OUT_ELEMS   (R_ROIS * C_TOTAL * OUT_SZ * OUT_SZ)   // 16777216
#define FEATP_ELEMS (N_BATCH * C_TOTAL * HH * WW)          // 2097152

// 3-tap merged weights for one axis / output coordinate u; the three clamped
// cell offsets (scaled by mulstep) are packed 8-bit each into .w.
// ratio=2: two samples' floors differ by <=1 -> 4 bilinear taps fit in 3
// consecutive cells {b, b+1, b+2}; clamped duplicates just sum weights.
__device__ __forceinline__ float4 axis_taps3(float lo, float binsz, int u,
                                             int mulstep) {
    float g0  = ((float)(2 * u) + 0.5f) * 0.5f;
    float s0  = lo + g0 * binsz;
    float s1  = s0 + 0.5f * binsz;
    float vm0 = (s0 >= -1.0f && s0 <= 16.0f) ? 0.5f : 0.0f;
    float vm1 = (s1 >= -1.0f && s1 <= 16.0f) ? 0.5f : 0.0f;
    float x0  = fminf(fmaxf(s0, 0.0f), 15.0f);
    float x1  = fminf(fmaxf(s1, 0.0f), 15.0f);
    float f0  = floorf(x0);
    float f1  = floorf(x1);
    float l0  = x0 - f0;
    float l1  = x1 - f1;
    bool  same = (f1 == f0);
    float4 rec;
    rec.x = (1.0f - l0) * vm0 + (same ? (1.0f - l1) * vm1 : 0.0f);
    rec.y = l0 * vm0 + (same ? l1 * vm1 : (1.0f - l1) * vm1);
    rec.z = same ? 0.0f : l1 * vm1;
    int b  = (int)f0;
    int o0 = b * mulstep;
    int o1 = min(b + 1, 15) * mulstep;
    int o2 = min(b + 2, 15) * mulstep;
    rec.w = __int_as_float(o0 | (o1 << 8) | (o2 << 16));
    return rec;
}

// ---------------------------------------------------------------------------
// Single fused, software-pipelined kernel (all-int32 indexing).
// Block = (8-channel chunk, batch nb), 256 threads; chunk split in 2 halves.
// Planes stored channel-pair interleaved (float2) -> y-pass is 3 LDS.64/pair.
//   LDG(h0) -> taps+ballot -> reduce h0 -> LDG(h1) -> STS h0 -> sync
//   -> roi(h0) [h1 in flight] -> reduce h1 -> STS h1 -> sync -> roi(h1)
// ---------------------------------------------------------------------------
__global__ __launch_bounds__(256, 5) void fused_kernel(
        const float* __restrict__ feat,
        const float* __restrict__ rois,
        float* __restrict__ out,
        float* __restrict__ featp) {
    const int nb    = blockIdx.y;
    const int cbase = blockIdx.x * C_PER;
    const int tid   = threadIdx.x;

    __shared__ float4 s_xtap[R_ROIS * 16];              // 8 KB
    __shared__ float4 s_ytap[R_ROIS * 16];              // 8 KB
    __shared__ float2 planes[2][NPAIR * PLANE_SM];      // 8.7 KB
    __shared__ int    s_list[R_ROIS];
    __shared__ int    s_cnt;

    // load mapping: one channel (of 4 per half) x one float4 pixel group
    const int c    = tid >> 6;          // 0..3
    const int q    = tid & 63;
    const int ppy  = q >> 2;            // plane row
    const int ppx  = (q & 3) * 4;       // first pixel in row
    const int nc0  = nb * C_TOTAL + cbase + c;           // int: fits easily
    const float4* src0 = (const float4*)feat + nc0 * (T_FR * 64) + q;

    // ---- issue half-0 loads ----
    float4 L[T_FR];
    #pragma unroll
    for (int t = 0; t < T_FR; t++) L[t] = __ldg(src0 + t * 64);

    // ---- tap table + roi list (overlaps h0 load latency) ----
    #pragma unroll
    for (int k = tid; k < R_ROIS * 16; k += 256) {
        const int r = k >> 4, u = k & 15;
        const float bx1 = rois[r * 5 + 1] * SCALE - 0.5f;
        const float by1 = rois[r * 5 + 2] * SCALE - 0.5f;
        const float bx2 = rois[r * 5 + 3] * SCALE - 0.5f;
        const float by2 = rois[r * 5 + 4] * SCALE - 0.5f;
        s_xtap[k] = axis_taps3(bx1, (bx2 - bx1) * (1.0f / OUT_SZ), u, 1);
        s_ytap[k] = axis_taps3(by1, (by2 - by1) * (1.0f / OUT_SZ), u, PSTR);
    }
    if (tid < 32) {
        int match = ((int)rois[tid * 5 + 0] == nb);
        unsigned m = __ballot_sync(0xffffffffu, match);
        if (match) s_list[__popc(m & ((1u << tid) - 1u))] = tid;
        if (tid == 0) s_cnt = __popc(m);
    }

    // interleaved STS target for this thread's channel (pair p, slot l)
    float* spbase0 = (float*)&planes[0][(c >> 1) * PLANE_SM + ppy * PSTR]
                   + ppx * 2 + (c & 1);
    float* spbase1 = (float*)&planes[1][(c >> 1) * PLANE_SM + ppy * PSTR]
                   + ppx * 2 + (c & 1);

    // ---- reduce half 0, write featp, start half-1 loads, stage smem ----
    float4 a = L[0];
    #pragma unroll
    for (int t = 1; t < T_FR; t++) {
        a.x += L[t].x; a.y += L[t].y; a.z += L[t].z; a.w += L[t].w;
    }
    a.x *= 0.125f; a.y *= 0.125f; a.z *= 0.125f; a.w *= 0.125f;
    __stcs((float4*)featp + nc0 * 64 + q, a);

    const float4* src1 = src0 + HALF * (T_FR * 64);
    #pragma unroll
    for (int t = 0; t < T_FR; t++) L[t] = __ldg(src1 + t * 64);

    spbase0[0] = a.x; spbase0[2] = a.y; spbase0[4] = a.z; spbase0[6] = a.w;
    __syncthreads();

    // ---- roi compute helpers ----
    const int lx = tid & 15;
    const int ly = tid >> 4;
    const int hi = tid & 16;
    const int nr = s_cnt;

    // ---- roi compute, half 0 (h1 loads in flight) ----
    for (int i = 0; i < nr; i++) {
        const int r = s_list[i];
        const float4 vx = s_xtap[r * 16 + lx];
        const float4 vy = s_ytap[r * 16 + ly];
        const int pk  = __float_as_int(vy.w);
        const int YR0 = (pk & 255) + lx;
        const int YR1 = ((pk >> 8) & 255) + lx;
        const int YR2 = ((pk >> 16) & 255) + lx;
        const int xk  = __float_as_int(vx.w);
        const int S0  = hi | (xk & 255);
        const int S1  = hi | ((xk >> 8) & 255);
        const int S2  = hi | ((xk >> 16) & 255);
        float* opb = out + (r * C_TOTAL + cbase) * (HH * WW) + tid;
        #pragma unroll
        for (int p = 0; p < NPAIR; p++) {
            const float2* pl = &planes[0][p * PLANE_SM];
            const float2 t0 = pl[YR0], t1 = pl[YR1], t2 = pl[YR2];
            float ta = fmaf(vy.z, t2.x, fmaf(vy.y, t1.x, vy.x * t0.x));
            float tb = fmaf(vy.z, t2.y, fmaf(vy.y, t1.y, vy.x * t0.y));
            float va =      vx.x * __shfl_sync(0xffffffffu, ta, S0);
            va = fmaf(vx.y, __shfl_sync(0xffffffffu, ta, S1), va);
            va = fmaf(vx.z, __shfl_sync(0xffffffffu, ta, S2), va);
            float vb =      vx.x * __shfl_sync(0xffffffffu, tb, S0);
            vb = fmaf(vx.y, __shfl_sync(0xffffffffu, tb, S1), vb);
            vb = fmaf(vx.z, __shfl_sync(0xffffffffu, tb, S2), vb);
            __stcs(opb + (2 * p)     * (HH * WW), va);
            __stcs(opb + (2 * p + 1) * (HH * WW), vb);
        }
    }

    // ---- reduce half 1, stage smem ----
    float4 b = L[0];
    #pragma unroll
    for (int t = 1; t < T_FR; t++) {
        b.x += L[t].x; b.y += L[t].y; b.z += L[t].z; b.w += L[t].w;
    }
    b.x *= 0.125f; b.y *= 0.125f; b.z *= 0.125f; b.w *= 0.125f;
    __stcs((float4*)featp + (nc0 + HALF) * 64 + q, b);
    spbase1[0] = b.x; spbase1[2] = b.y; spbase1[4] = b.z; spbase1[6] = b.w;
    __syncthreads();

    // ---- roi compute, half 1 ----
    for (int i = 0; i < nr; i++) {
        const int r = s_list[i];
        const float4 vx = s_xtap[r * 16 + lx];
        const float4 vy = s_ytap[r * 16 + ly];
        const int pk  = __float_as_int(vy.w);
        const int YR0 = (pk & 255) + lx;
        const int YR1 = ((pk >> 8) & 255) + lx;
        const int YR2 = ((pk >> 16) & 255) + lx;
        const int xk  = __float_as_int(vx.w);
        const int S0  = hi | (xk & 255);
        const int S1  = hi | ((xk >> 8) & 255);
        const int S2  = hi | ((xk >> 16) & 255);
        float* opb = out + (r * C_TOTAL + cbase + HALF) * (HH * WW) + tid;
        #pragma unroll
        for (int p = 0; p < NPAIR; p++) {
            const float2* pl = &planes[1][p * PLANE_SM];
            const float2 t0 = pl[YR0], t1 = pl[YR1], t2 = pl[YR2];
            float ta = fmaf(vy.z, t2.x, fmaf(vy.y, t1.x, vy.x * t0.x));
            float tb = fmaf(vy.z, t2.y, fmaf(vy.y, t1.y, vy.x * t0.y));
            float va =      vx.x * __shfl_sync(0xffffffffu, ta, S0);
            va = fmaf(vx.y, __shfl_sync(0xffffffffu, ta, S1), va);
            va = fmaf(vx.z, __shfl_sync(0xffffffffu, ta, S2), va);
            float vb =      vx.x * __shfl_sync(0xffffffffu, tb, S0);
            vb = fmaf(vx.y, __shfl_sync(0xffffffffu, tb, S1), vb);
            vb = fmaf(vx.z, __shfl_sync(0xffffffffu, tb, S2), vb);
            __stcs(opb + (2 * p)     * (HH * WW), va);
            __stcs(opb + (2 * p + 1) * (HH * WW), vb);
        }
    }
}

// ---------------------------------------------------------------------------
extern "C" void kernel_launch(void* const* d_in, const int* in_sizes, int n_in,
                              void* d_out, int out_size) {
    const float* feat = (const float*)d_in[0];
    const float* rois = (const float*)d_in[1];
    float* out   = (float*)d_out;
    float* featp = out + OUT_ELEMS;   // feat_p is the 2nd tuple element

    dim3 grid(C_CHUNKS, N_BATCH);     // 256 x 4 = 1024 blocks
    fused_kernel<<<grid, 256>>>(feat, rois, out, featp);
}